// round 4
// baseline (speedup 1.0000x reference)
#include <cuda_runtime.h>
#include <cstdint>

// Problem constants
#define HW_     16384            // H*W = 128*128
#define CHW_    4194304          // C*H*W = 256*16384
#define NB_     8                // batch
#define JD_     32768            // C*H*W / W = 32768 (reshaped inner dim)
#define SPLITK_ 128              // split-K factor for logit GEMM
#define KCH_    256              // 32768 / 128

// Output chunk offsets (floats) for the concatenated tuple
// (out_w, x_Qw, x_Kw, x_Vw, gamma, att)
#define OFF_OUTW  0
#define OFF_QW    33554432
#define OFF_KW    67108864
#define OFF_VW    100663296
#define OFF_GAMMA 134217728
#define OFF_ATT   134217729
#define FULL_SIZE 134348801

// ---------------- device-global scratch (no allocations allowed) -----------
__device__ float g_kscr[(size_t)NB_ * CHW_];             // K conv, normal layout
__device__ float g_vscr[(size_t)NB_ * CHW_];             // V conv, normal layout
__device__ float g_psum[(size_t)NB_ * SPLITK_ * 16384];  // split-K partial logits
__device__ float g_att [(size_t)NB_ * 16384];            // softmax result (16B aligned)
// fallback buffers in case d_out only holds out_w
__device__ float g_qfb [(size_t)NB_ * CHW_];
__device__ float g_ktfb[(size_t)NB_ * CHW_];
__device__ float g_vtfb[(size_t)NB_ * CHW_];

// ---------------- 128x128x16 double-buffered fp32 SGEMM core ---------------
// A: row-major, block tile rows [0,128) of the passed pointer, lda given
// B: row-major, block tile cols [0,128) of the passed pointer, ldb given
// K multiple of 16. 256 threads. smem: sA/sB each 2*2048 floats.
__device__ __forceinline__ void sgemm_block_core(
    const float* __restrict__ A, int lda,
    const float* __restrict__ B, int ldb,
    int K, float acc[8][8], float* sA, float* sB)
{
    const int tid  = threadIdx.x;
    const int aRow = tid >> 2;          // 0..63  (and +64)
    const int aCol = (tid & 3) << 2;    // 0,4,8,12
    const int bRow = tid >> 5;          // 0..7   (and +8)
    const int bCol = (tid & 31) << 2;   // 0..124
    const int nT   = K >> 4;

    float4 ra0, ra1, rb0, rb1;

    // prologue: tile 0 -> buffer 0
    ra0 = *(const float4*)(A + (size_t)aRow      * lda + aCol);
    ra1 = *(const float4*)(A + (size_t)(aRow+64) * lda + aCol);
    rb0 = *(const float4*)(B + (size_t)bRow      * ldb + bCol);
    rb1 = *(const float4*)(B + (size_t)(bRow+8)  * ldb + bCol);
    {
        float* s = sA;
        s[(aCol+0)*128 + aRow]    = ra0.x;
        s[(aCol+1)*128 + aRow]    = ra0.y;
        s[(aCol+2)*128 + aRow]    = ra0.z;
        s[(aCol+3)*128 + aRow]    = ra0.w;
        s[(aCol+0)*128 + aRow+64] = ra1.x;
        s[(aCol+1)*128 + aRow+64] = ra1.y;
        s[(aCol+2)*128 + aRow+64] = ra1.z;
        s[(aCol+3)*128 + aRow+64] = ra1.w;
        *(float4*)(sB + bRow*128     + bCol) = rb0;
        *(float4*)(sB + (bRow+8)*128 + bCol) = rb1;
    }
    __syncthreads();

    const int tx = tid & 15, ty = tid >> 4;

    for (int kt = 0; kt < nT; kt++) {
        if (kt + 1 < nT) {
            const float* Ak = A + ((kt + 1) << 4);
            const float* Bk = B + (size_t)((kt + 1) << 4) * ldb;
            ra0 = *(const float4*)(Ak + (size_t)aRow      * lda + aCol);
            ra1 = *(const float4*)(Ak + (size_t)(aRow+64) * lda + aCol);
            rb0 = *(const float4*)(Bk + (size_t)bRow      * ldb + bCol);
            rb1 = *(const float4*)(Bk + (size_t)(bRow+8)  * ldb + bCol);
        }
        const float* cA = sA + (kt & 1) * 2048;
        const float* cB = sB + (kt & 1) * 2048;
        #pragma unroll
        for (int kk = 0; kk < 16; kk++) {
            float4 a0 = *(const float4*)(cA + kk*128 + ty*8);
            float4 a1 = *(const float4*)(cA + kk*128 + ty*8 + 4);
            float4 b0 = *(const float4*)(cB + kk*128 + tx*8);
            float4 b1 = *(const float4*)(cB + kk*128 + tx*8 + 4);
            float av[8] = {a0.x,a0.y,a0.z,a0.w,a1.x,a1.y,a1.z,a1.w};
            float bw[8] = {b0.x,b0.y,b0.z,b0.w,b1.x,b1.y,b1.z,b1.w};
            #pragma unroll
            for (int i = 0; i < 8; i++)
                #pragma unroll
                for (int j = 0; j < 8; j++)
                    acc[i][j] = fmaf(av[i], bw[j], acc[i][j]);
        }
        if (kt + 1 < nT) {
            float* s = sA + ((kt + 1) & 1) * 2048;
            s[(aCol+0)*128 + aRow]    = ra0.x;
            s[(aCol+1)*128 + aRow]    = ra0.y;
            s[(aCol+2)*128 + aRow]    = ra0.z;
            s[(aCol+3)*128 + aRow]    = ra0.w;
            s[(aCol+0)*128 + aRow+64] = ra1.x;
            s[(aCol+1)*128 + aRow+64] = ra1.y;
            s[(aCol+2)*128 + aRow+64] = ra1.z;
            s[(aCol+3)*128 + aRow+64] = ra1.w;
            float* sb = sB + ((kt + 1) & 1) * 2048;
            *(float4*)(sb + bRow*128     + bCol) = rb0;
            *(float4*)(sb + (bRow+8)*128 + bCol) = rb1;
            __syncthreads();
        }
    }
}

// ---------------- kernel 1: fused QKV 1x1 conv + bias + ReLU ---------------
// grid (128, 6, 8): x = n-tile, y = (m-tile | op*2), z = batch
__global__ __launch_bounds__(256, 2) void conv_qkv_kernel(
    const float* __restrict__ x,
    const float* __restrict__ Wq, const float* __restrict__ bq,
    const float* __restrict__ Wk, const float* __restrict__ bk,
    const float* __restrict__ Wv, const float* __restrict__ bv,
    float* __restrict__ qdst)
{
    __shared__ float smem[8192];
    if (!qdst) qdst = g_qfb;
    const int b  = blockIdx.z;
    const int op = blockIdx.y >> 1;
    const int m0 = (blockIdx.y & 1) << 7;
    const int n0 = blockIdx.x << 7;

    const float* Wsel = (op == 0) ? Wq : (op == 1) ? Wk : Wv;
    const float* bsel = (op == 0) ? bq : (op == 1) ? bk : bv;
    float*       dst  = (op == 0) ? qdst : (op == 1) ? g_kscr : g_vscr;

    const float* A = Wsel + (size_t)m0 * 256;
    const float* B = x + (size_t)b * CHW_ + n0;
    dst += (size_t)b * CHW_;

    float acc[8][8];
    #pragma unroll
    for (int i = 0; i < 8; i++)
        #pragma unroll
        for (int j = 0; j < 8; j++) acc[i][j] = 0.f;

    sgemm_block_core(A, 256, B, HW_, 256, acc, smem, smem + 4096);

    const int tx = threadIdx.x & 15, ty = threadIdx.x >> 4;
    #pragma unroll
    for (int i = 0; i < 8; i++) {
        const int m = m0 + ty * 8 + i;
        const float bb = __ldg(bsel + m);
        float* row = dst + (size_t)m * HW_ + n0 + tx * 8;
        float4 v0, v1;
        v0.x = fmaxf(acc[i][0] + bb, 0.f);
        v0.y = fmaxf(acc[i][1] + bb, 0.f);
        v0.z = fmaxf(acc[i][2] + bb, 0.f);
        v0.w = fmaxf(acc[i][3] + bb, 0.f);
        v1.x = fmaxf(acc[i][4] + bb, 0.f);
        v1.y = fmaxf(acc[i][5] + bb, 0.f);
        v1.z = fmaxf(acc[i][6] + bb, 0.f);
        v1.w = fmaxf(acc[i][7] + bb, 0.f);
        *(float4*)row       = v0;
        *(float4*)(row + 4) = v1;
    }
}

// ---------------- kernel 2: K/V layout transpose into x_Kw / x_Vw ----------
// in:  scr[b][c][p]   out: [b][j][i] with j = (c&1)*16384 + p, i = c>>1
// grid (512, 4, 32): x = p-tile, y = i-tile, z = (b<<2)|(par<<1)|kv
__global__ void transpose_kv_kernel(float* __restrict__ ktw, float* __restrict__ vtw)
{
    __shared__ float tile[32][33];
    if (!ktw) ktw = g_ktfb;
    if (!vtw) vtw = g_vtfb;
    const int z   = blockIdx.z;
    const int kv  = z & 1;
    const int par = (z >> 1) & 1;
    const int b   = z >> 2;
    const float* src = (kv ? g_vscr : g_kscr) + (size_t)b * CHW_;
    float*       dst = (kv ? vtw    : ktw   ) + (size_t)b * CHW_;
    const int p0 = blockIdx.x << 5, i0 = blockIdx.y << 5;
    const int tx = threadIdx.x, ty = threadIdx.y;
    #pragma unroll
    for (int r = 0; r < 4; r++) {
        const int ii = ty + r * 8;
        tile[ii][tx] = src[(size_t)(2 * (i0 + ii) + par) * HW_ + p0 + tx];
    }
    __syncthreads();
    #pragma unroll
    for (int r = 0; r < 4; r++) {
        const int pp = ty + r * 8;
        dst[(size_t)(par * 16384 + p0 + pp) * 128 + i0 + tx] = tile[tx][pp];
    }
}

// ---------------- kernel 3: split-K logit GEMM  att_raw = Qr * Kr^T --------
// grid (SPLITK_, 8): x = k-split s, y = batch. Partial [128x128] -> g_psum.
__global__ __launch_bounds__(256, 2) void att_gemm_kernel(
    const float* __restrict__ q, const float* __restrict__ kt)
{
    __shared__ float smem[8192];
    if (!q)  q  = g_qfb;
    if (!kt) kt = g_ktfb;
    const int s = blockIdx.x, b = blockIdx.y;
    const float* A = q  + (size_t)b * CHW_ + (size_t)s * KCH_;        // lda = 32768
    const float* B = kt + (size_t)b * CHW_ + (size_t)s * KCH_ * 128;  // ldb = 128

    float acc[8][8];
    #pragma unroll
    for (int i = 0; i < 8; i++)
        #pragma unroll
        for (int j = 0; j < 8; j++) acc[i][j] = 0.f;

    sgemm_block_core(A, JD_, B, 128, KCH_, acc, smem, smem + 4096);

    float* Cp = g_psum + ((size_t)b * SPLITK_ + s) * 16384;
    const int tx = threadIdx.x & 15, ty = threadIdx.x >> 4;
    #pragma unroll
    for (int i = 0; i < 8; i++) {
        float* row = Cp + (size_t)(ty * 8 + i) * 128 + tx * 8;
        float4 v0 = {acc[i][0], acc[i][1], acc[i][2], acc[i][3]};
        float4 v1 = {acc[i][4], acc[i][5], acc[i][6], acc[i][7]};
        *(float4*)row       = v0;
        *(float4*)(row + 4) = v1;
    }
}

// ---------------- kernel 4: Kahan split-K reduce + softmax over axis=1 -----
// grid (128, 8): x = i' (column), y = batch; 128 threads = i (row)
__global__ void softmax_kernel(float* __restrict__ attw,
                               float* __restrict__ gmw,
                               const float* __restrict__ gamma)
{
    const int b = blockIdx.y, ip = blockIdx.x, i = threadIdx.x;
    const float* base = g_psum + (size_t)b * SPLITK_ * 16384 + (size_t)i * 128 + ip;
    float s = 0.f, comp = 0.f;
    for (int t = 0; t < SPLITK_; t++) {
        float y = __fsub_rn(base[(size_t)t * 16384], comp);
        float u = __fadd_rn(s, y);
        comp = __fsub_rn(__fsub_rn(u, s), y);
        s = u;
    }
    __shared__ float red[128];
    red[i] = s;
    __syncthreads();
    for (int off = 64; off > 0; off >>= 1) {
        if (i < off) red[i] = fmaxf(red[i], red[i + off]);
        __syncthreads();
    }
    const float mx = red[0];
    __syncthreads();
    const float e = expf(s - mx);
    red[i] = e;
    __syncthreads();
    for (int off = 64; off > 0; off >>= 1) {
        if (i < off) red[i] += red[i + off];
        __syncthreads();
    }
    const float r = e / red[0];
    g_att[(size_t)b * 16384 + (size_t)i * 128 + ip] = r;
    if (attw) attw[(size_t)b * 16384 + (size_t)i * 128 + ip] = r;
    if (gmw && b == 0 && ip == 0 && i == 0) *gmw = __ldg(gamma);
}

// ---------------- kernel 5: out1 = x_Vw @ att, scaled by gamma -------------
// grid (256, 8): x = m-tile (of 32768), y = batch
__global__ __launch_bounds__(256, 2) void out_gemm_kernel(
    const float* __restrict__ vt, float* __restrict__ outw,
    const float* __restrict__ gamma)
{
    __shared__ float smem[8192];
    if (!vt) vt = g_vtfb;
    const int b  = blockIdx.y;
    const int m0 = blockIdx.x << 7;
    const float* A = vt + (size_t)b * CHW_ + (size_t)m0 * 128;  // lda = 128
    const float* B = g_att + (size_t)b * 16384;                 // ldb = 128

    float acc[8][8];
    #pragma unroll
    for (int i = 0; i < 8; i++)
        #pragma unroll
        for (int j = 0; j < 8; j++) acc[i][j] = 0.f;

    sgemm_block_core(A, 128, B, 128, 128, acc, smem, smem + 4096);

    const float g = __ldg(gamma);
    float* base = outw + (size_t)b * CHW_;
    const int tx = threadIdx.x & 15, ty = threadIdx.x >> 4;
    #pragma unroll
    for (int i = 0; i < 8; i++) {
        float* row = base + (size_t)(m0 + ty * 8 + i) * 128 + tx * 8;
        float4 v0 = {acc[i][0] * g, acc[i][1] * g, acc[i][2] * g, acc[i][3] * g};
        float4 v1 = {acc[i][4] * g, acc[i][5] * g, acc[i][6] * g, acc[i][7] * g};
        *(float4*)row       = v0;
        *(float4*)(row + 4) = v1;
    }
}

// ---------------- launch ---------------------------------------------------
extern "C" void kernel_launch(void* const* d_in, const int* in_sizes, int n_in,
                              void* d_out, int out_size)
{
    const float* x  = (const float*)d_in[0];
    const float* Wq = (const float*)d_in[1];
    const float* bq = (const float*)d_in[2];
    const float* Wk = (const float*)d_in[3];
    const float* bk = (const float*)d_in[4];
    const float* Wv = (const float*)d_in[5];
    const float* bv = (const float*)d_in[6];
    const float* gm = (const float*)d_in[7];
    float* out = (float*)d_out;

    const bool full = (out_size >= FULL_SIZE);
    float* outw = out;  // out_w is the first tuple element either way
    float* qw   = full ? out + OFF_QW    : nullptr;
    float* ktw  = full ? out + OFF_KW    : nullptr;
    float* vtw  = full ? out + OFF_VW    : nullptr;
    float* gmw  = full ? out + OFF_GAMMA : nullptr;
    float* attw = full ? out + OFF_ATT   : nullptr;

    conv_qkv_kernel<<<dim3(128, 6, 8), 256>>>(x, Wq, bq, Wk, bk, Wv, bv, qw);
    transpose_kv_kernel<<<dim3(512, 4, 32), dim3(32, 8)>>>(ktw, vtw);
    att_gemm_kernel<<<dim3(SPLITK_, 8), 256>>>(qw, ktw);
    softmax_kernel<<<dim3(128, 8), 128>>>(attw, gmw, gm);
    out_gemm_kernel<<<dim3(256, 8), 256>>>(vtw, outw, gm);
}